// round 1
// baseline (speedup 1.0000x reference)
#include <cuda_runtime.h>
#include <cuda_bf16.h>
#include <math.h>

// Problem constants
#define NROI 128
#define CCH  256
#define ECH  256
#define SS   3
#define LLV  5
#define M_GEMM (NROI*9)      // 1152
#define K_GEMM (CCH*9)       // 2304
#define N_GEMM ECH           // 256

#define BM 128
#define BN 128
#define BK 8
#define SPLITK 8
#define KSLICE (K_GEMM/SPLITK)   // 288

// Scratch (device globals; no runtime allocation allowed)
__device__ __align__(16) float g_X[(size_t)M_GEMM * K_GEMM];            // 10.6 MB im2col
__device__ __align__(16) float g_hpart[(size_t)SPLITK * M_GEMM * N_GEMM]; // 9.4 MB split-K partials

// ---------------------------------------------------------------------------
// K1: ROI-align (bilinear, exactly mirroring the reference math) + im2col.
// grid = NROI blocks, 256 threads, thread = channel.
// ---------------------------------------------------------------------------
__global__ void __launch_bounds__(256) k_roi_im2col(
    const float* __restrict__ fm, const float* __restrict__ boxes,
    const int* __restrict__ batch_idx, const int* __restrict__ level_idx)
{
    const int n = blockIdx.x;
    const int c = threadIdx.x;

    const int lvl = level_idx[n];
    const int b   = batch_idx[n];
    const float stride = (float)(8 << lvl);      // 8,16,32,64,128
    const float hv     = (float)(128 >> lvl);    // 128,64,32,16,8
    const float scale  = 1.0f / stride;

    const float x1 = boxes[n*4+0] * scale;
    const float y1 = boxes[n*4+1] * scale;
    const float x2 = boxes[n*4+2] * scale;
    const float y2 = boxes[n*4+3] * scale;
    const float roi_w = fmaxf(x2 - x1, 1.0f);
    const float roi_h = fmaxf(y2 - y1, 1.0f);

    const float* __restrict__ plane =
        fm + ((size_t)(lvl*2 + b) * CCH + c) * 128 * 128;
    const int hi = (int)(hv - 1.0f);

    float v[3][3];
    #pragma unroll
    for (int py = 0; py < 3; py++) {
        const float offy = ((float)py + 0.5f) / 3.0f;
        const float y = y1 + offy * roi_h;
        #pragma unroll
        for (int px = 0; px < 3; px++) {
            const float offx = ((float)px + 0.5f) / 3.0f;
            const float x = x1 + offx * roi_w;
            const bool valid = (y > -1.0f) && (y < hv) && (x > -1.0f) && (x < hv);
            const float yc = fminf(fmaxf(y, 0.0f), hv - 1.0f);
            const float xc = fminf(fmaxf(x, 0.0f), hv - 1.0f);
            const int y0 = (int)floorf(yc);
            const int x0 = (int)floorf(xc);
            const int y1i = min(y0 + 1, hi);
            const int x1i = min(x0 + 1, hi);
            const float ly = yc - (float)y0;
            const float lx = xc - (float)x0;
            const float v00 = plane[y0 * 128 + x0];
            const float v01 = plane[y0 * 128 + x1i];
            const float v10 = plane[y1i * 128 + x0];
            const float v11 = plane[y1i * 128 + x1i];
            float val = (1.0f-ly)*(1.0f-lx)*v00 + (1.0f-ly)*lx*v01
                      + ly*(1.0f-lx)*v10 + ly*lx*v11;
            v[py][px] = valid ? val : 0.0f;
        }
    }

    // im2col write: X[(n*9+p)][c*9 + ky*3+kx] = padded roi value
    #pragma unroll
    for (int py = 0; py < 3; py++) {
        #pragma unroll
        for (int px = 0; px < 3; px++) {
            const int p = py * 3 + px;
            float* __restrict__ row = g_X + ((size_t)(n*9 + p)) * K_GEMM + c * 9;
            #pragma unroll
            for (int ky = 0; ky < 3; ky++) {
                #pragma unroll
                for (int kx = 0; kx < 3; kx++) {
                    const int iy = py + ky - 1;
                    const int ix = px + kx - 1;
                    float val = (iy >= 0 && iy < 3 && ix >= 0 && ix < 3) ? v[iy][ix] : 0.0f;
                    row[ky*3 + kx] = val;
                }
            }
        }
    }
}

// ---------------------------------------------------------------------------
// K2: fp32 GEMM  h[m,e] = sum_k X[m,k] * conv_w[e,k]   (B used transposed)
// Tile 128x128, BK=8, 8x8 microtile, split-K=8, grid (2,9,8) = 144 blocks.
// Writes deterministic partials (no atomics).
// ---------------------------------------------------------------------------
__global__ void __launch_bounds__(256) k_conv_gemm(const float* __restrict__ conv_w)
{
    __shared__ float As[BK][BM];
    __shared__ float Bs[BK][BN];

    const int tid = threadIdx.x;
    const int e0 = blockIdx.x * BN;
    const int m0 = blockIdx.y * BM;
    const int k0 = blockIdx.z * KSLICE;

    const int lr = tid >> 1;          // 0..127 (row being loaded)
    const int lc = (tid & 1) * 4;     // 0 or 4 (k offset within BK)
    const int tr = (tid >> 4) << 3;   // microtile row base
    const int tc = (tid & 15) << 3;   // microtile col base

    float acc[8][8];
    #pragma unroll
    for (int i = 0; i < 8; i++)
        #pragma unroll
        for (int j = 0; j < 8; j++) acc[i][j] = 0.0f;

    const float* __restrict__ Aptr = g_X    + (size_t)(m0 + lr) * K_GEMM + k0 + lc;
    const float* __restrict__ Bptr = conv_w + (size_t)(e0 + lr) * K_GEMM + k0 + lc;

    for (int kt = 0; kt < KSLICE; kt += BK) {
        const float4 a4 = *(const float4*)(Aptr + kt);
        const float4 b4 = *(const float4*)(Bptr + kt);
        As[lc+0][lr] = a4.x; As[lc+1][lr] = a4.y; As[lc+2][lr] = a4.z; As[lc+3][lr] = a4.w;
        Bs[lc+0][lr] = b4.x; Bs[lc+1][lr] = b4.y; Bs[lc+2][lr] = b4.z; Bs[lc+3][lr] = b4.w;
        __syncthreads();

        #pragma unroll
        for (int kk = 0; kk < BK; kk++) {
            float a[8], bb[8];
            *(float4*)(a)     = *(const float4*)(&As[kk][tr]);
            *(float4*)(a + 4) = *(const float4*)(&As[kk][tr + 4]);
            *(float4*)(bb)    = *(const float4*)(&Bs[kk][tc]);
            *(float4*)(bb + 4)= *(const float4*)(&Bs[kk][tc + 4]);
            #pragma unroll
            for (int i = 0; i < 8; i++)
                #pragma unroll
                for (int j = 0; j < 8; j++)
                    acc[i][j] = fmaf(a[i], bb[j], acc[i][j]);
        }
        __syncthreads();
    }

    float* __restrict__ hp = g_hpart + (size_t)blockIdx.z * (M_GEMM * N_GEMM);
    #pragma unroll
    for (int i = 0; i < 8; i++) {
        float* dst = hp + (size_t)(m0 + tr + i) * N_GEMM + e0 + tc;
        *(float4*)(dst)     = make_float4(acc[i][0], acc[i][1], acc[i][2], acc[i][3]);
        *(float4*)(dst + 4) = make_float4(acc[i][4], acc[i][5], acc[i][6], acc[i][7]);
    }
}

// ---------------------------------------------------------------------------
// K3: per-roi epilogue. grid = NROI, 256 threads (thread = channel e).
// split-K reduce -> GroupNorm(8 groups; warp == group) -> relu -> mean(9)
// -> head GEMV+relu -> spat GEMV+relu -> +sym_emb -> fuse GEMV+relu.
// ---------------------------------------------------------------------------
__global__ void __launch_bounds__(256) k_epilogue(
    const float* __restrict__ boxes,
    const float* __restrict__ gn_scale, const float* __restrict__ gn_bias,
    const float* __restrict__ head_w,   const float* __restrict__ head_b,
    const float* __restrict__ spat_w,   const float* __restrict__ spat_b,
    const float* __restrict__ sym_emb,
    const float* __restrict__ fuse_w,   const float* __restrict__ fuse_b,
    const int*   __restrict__ sym_ids,
    float* __restrict__ out)
{
    const int n = blockIdx.x;
    const int e = threadIdx.x;

    // split-K reduction: h[n, e, p]
    float hvp[9];
    #pragma unroll
    for (int p = 0; p < 9; p++) {
        float s = 0.0f;
        #pragma unroll
        for (int sp = 0; sp < SPLITK; sp++)
            s += g_hpart[(size_t)sp * (M_GEMM * N_GEMM) + (size_t)(n*9 + p) * N_GEMM + e];
        hvp[p] = s;
    }

    // GroupNorm: group = e/32 == warp. Two-pass (mean, then centered var).
    float lsum = 0.0f;
    #pragma unroll
    for (int p = 0; p < 9; p++) lsum += hvp[p];
    #pragma unroll
    for (int o = 16; o > 0; o >>= 1) lsum += __shfl_xor_sync(0xffffffffu, lsum, o);
    const float mean = lsum * (1.0f / 288.0f);

    float lsq = 0.0f;
    #pragma unroll
    for (int p = 0; p < 9; p++) { float d = hvp[p] - mean; lsq += d * d; }
    #pragma unroll
    for (int o = 16; o > 0; o >>= 1) lsq += __shfl_xor_sync(0xffffffffu, lsq, o);
    const float var = lsq * (1.0f / 288.0f);
    const float inv = rsqrtf(var + 1e-5f);

    const float sc = gn_scale[e];
    const float bi = gn_bias[e];
    float acc = 0.0f;
    #pragma unroll
    for (int p = 0; p < 9; p++)
        acc += fmaxf((hvp[p] - mean) * inv * sc + bi, 0.0f);
    const float sval = acc * (1.0f / 9.0f);

    __shared__ float sbuf[256];
    sbuf[e] = sval;
    __syncthreads();

    // head_out[e] = relu( sum_j s[j] * head_w[e, j] + head_b[e] )
    float ho = head_b[e];
    const float* __restrict__ hw = head_w + (size_t)e * 256;
    #pragma unroll 8
    for (int j = 0; j < 256; j += 4) {
        const float4 w = *(const float4*)(hw + j);
        ho += sbuf[j]   * w.x + sbuf[j+1] * w.y
            + sbuf[j+2] * w.z + sbuf[j+3] * w.w;
    }
    ho = fmaxf(ho, 0.0f);

    // spat
    const float b0 = boxes[n*4+0], b1 = boxes[n*4+1], b2 = boxes[n*4+2], b3 = boxes[n*4+3];
    float sp = spat_b[e] + b0 * spat_w[e*4+0] + b1 * spat_w[e*4+1]
                         + b2 * spat_w[e*4+2] + b3 * spat_w[e*4+3];
    sp = fmaxf(sp, 0.0f);

    const int sym = sym_ids[n];
    const float fused = ho + sp + sym_emb[sym * 256 + e];

    __syncthreads();          // done reading sbuf as s[]
    sbuf[e] = fused;
    __syncthreads();

    // out[n, e] = relu( sum_j fused[j] * fuse_w[sym, e, j] + fuse_b[sym, e] )
    float o = fuse_b[sym * 256 + e];
    const float* __restrict__ fw = fuse_w + ((size_t)sym * 256 + e) * 256;
    #pragma unroll 8
    for (int j = 0; j < 256; j += 4) {
        const float4 w = *(const float4*)(fw + j);
        o += sbuf[j]   * w.x + sbuf[j+1] * w.y
           + sbuf[j+2] * w.z + sbuf[j+3] * w.w;
    }
    out[(size_t)n * 256 + e] = fmaxf(o, 0.0f);
}

// ---------------------------------------------------------------------------
extern "C" void kernel_launch(void* const* d_in, const int* in_sizes, int n_in,
                              void* d_out, int out_size)
{
    const float* fm        = (const float*)d_in[0];
    const float* boxes     = (const float*)d_in[1];
    const float* conv_w    = (const float*)d_in[2];
    const float* gn_scale  = (const float*)d_in[3];
    const float* gn_bias   = (const float*)d_in[4];
    const float* head_w    = (const float*)d_in[5];
    const float* head_b    = (const float*)d_in[6];
    const float* spat_w    = (const float*)d_in[7];
    const float* spat_b    = (const float*)d_in[8];
    const float* sym_emb   = (const float*)d_in[9];
    const float* fuse_w    = (const float*)d_in[10];
    const float* fuse_b    = (const float*)d_in[11];
    const int*   batch_idx = (const int*)d_in[12];
    const int*   level_idx = (const int*)d_in[13];
    const int*   sym_ids   = (const int*)d_in[14];
    float* out = (float*)d_out;

    k_roi_im2col<<<NROI, 256>>>(fm, boxes, batch_idx, level_idx);

    dim3 g2(N_GEMM / BN, M_GEMM / BM, SPLITK);   // (2, 9, 8)
    k_conv_gemm<<<g2, 256>>>(conv_w);

    k_epilogue<<<NROI, 256>>>(boxes, gn_scale, gn_bias, head_w, head_b,
                              spat_w, spat_b, sym_emb, fuse_w, fuse_b,
                              sym_ids, out);
}

// round 3
// speedup vs baseline: 1.4003x; 1.4003x over previous
#include <cuda_runtime.h>
#include <cuda_bf16.h>
#include <math.h>
#include <cstdint>

// ---------------- problem constants ----------------
#define NROI 128
#define CCH  256
#define ECH  256
#define M_GEMM (NROI*9)      // 1152
#define K_GEMM (CCH*9)       // 2304
#define N_GEMM ECH           // 256

#define SPLITK 8
#define KSLICE (K_GEMM/SPLITK)   // 288
#define BK     32
#define NSTAGE (KSLICE/BK)       // 9
#define SROW   36                // padded smem row stride (floats)

// ---------------- device scratch (no runtime alloc allowed) ----------------
__device__ __align__(256) float g_R[(size_t)NROI * CCH * 9];               // 1.18 MB
__device__ __align__(256) float g_A[(size_t)M_GEMM * K_GEMM];              // 10.6 MB
__device__ __align__(256) float g_hpart[(size_t)SPLITK * M_GEMM * N_GEMM]; // 9.4 MB

__device__ __forceinline__ float f2tf32(float x) {
    float r;
    asm("cvt.rna.tf32.f32 %0, %1;" : "=f"(r) : "f"(x));
    return r;
}

__device__ __forceinline__ void mma_tf32(float c[4],
                                         uint32_t a0, uint32_t a1, uint32_t a2, uint32_t a3,
                                         uint32_t b0, uint32_t b1) {
    asm volatile(
        "mma.sync.aligned.m16n8k8.row.col.f32.tf32.tf32.f32 "
        "{%0,%1,%2,%3}, {%4,%5,%6,%7}, {%8,%9}, {%0,%1,%2,%3};"
        : "+f"(c[0]), "+f"(c[1]), "+f"(c[2]), "+f"(c[3])
        : "r"(a0), "r"(a1), "r"(a2), "r"(a3), "r"(b0), "r"(b1));
}

// ---------------------------------------------------------------------------
// K1a: ROI-align -> compact R[n][c][9].  grid (NROI, 4) x 64 threads.
// ---------------------------------------------------------------------------
__global__ void __launch_bounds__(64) k_roi(
    const float* __restrict__ fm, const float* __restrict__ boxes,
    const int* __restrict__ batch_idx, const int* __restrict__ level_idx)
{
    const int n = blockIdx.x;
    const int c = blockIdx.y * 64 + threadIdx.x;

    const int lvl = level_idx[n];
    const int b   = batch_idx[n];
    const float stride = (float)(8 << lvl);
    const float hv     = (float)(128 >> lvl);
    const float scale  = 1.0f / stride;

    const float x1 = boxes[n*4+0] * scale;
    const float y1 = boxes[n*4+1] * scale;
    const float x2 = boxes[n*4+2] * scale;
    const float y2 = boxes[n*4+3] * scale;
    const float roi_w = fmaxf(x2 - x1, 1.0f);
    const float roi_h = fmaxf(y2 - y1, 1.0f);

    const float* __restrict__ plane =
        fm + ((size_t)(lvl*2 + b) * CCH + c) * 128 * 128;
    const int hi = (int)(hv - 1.0f);

    float* __restrict__ r = g_R + ((size_t)n * CCH + c) * 9;

    #pragma unroll
    for (int py = 0; py < 3; py++) {
        const float offy = ((float)py + 0.5f) / 3.0f;
        const float y = y1 + offy * roi_h;
        #pragma unroll
        for (int px = 0; px < 3; px++) {
            const float offx = ((float)px + 0.5f) / 3.0f;
            const float x = x1 + offx * roi_w;
            const bool valid = (y > -1.0f) && (y < hv) && (x > -1.0f) && (x < hv);
            const float yc = fminf(fmaxf(y, 0.0f), hv - 1.0f);
            const float xc = fminf(fmaxf(x, 0.0f), hv - 1.0f);
            const int y0 = (int)floorf(yc);
            const int x0 = (int)floorf(xc);
            const int y1i = min(y0 + 1, hi);
            const int x1i = min(x0 + 1, hi);
            const float ly = yc - (float)y0;
            const float lx = xc - (float)x0;
            const float v00 = plane[y0 * 128 + x0];
            const float v01 = plane[y0 * 128 + x1i];
            const float v10 = plane[y1i * 128 + x0];
            const float v11 = plane[y1i * 128 + x1i];
            float val = (1.0f-ly)*(1.0f-lx)*v00 + (1.0f-ly)*lx*v01
                      + ly*(1.0f-lx)*v10 + ly*lx*v11;
            r[py*3 + px] = valid ? val : 0.0f;
        }
    }
}

// ---------------------------------------------------------------------------
// K1b: expand R -> im2col A[m=(n,p)][k=(c,kk)].  grid = M_GEMM blocks x 256.
// ---------------------------------------------------------------------------
__global__ void __launch_bounds__(256) k_im2col()
{
    const int m = blockIdx.x;
    const int n = m / 9;
    const int p = m - n * 9;
    const int py = p / 3, px = p - py * 3;
    const float* __restrict__ rn = g_R + (size_t)n * CCH * 9;
    float* __restrict__ row = g_A + (size_t)m * K_GEMM;

    #pragma unroll
    for (int j = 0; j < K_GEMM / 256; j++) {
        const int k = j * 256 + threadIdx.x;
        const int c = k / 9;
        const int kk = k - c * 9;
        const int ky = kk / 3, kx = kk - ky * 3;
        const int iy = py + ky - 1;
        const int ix = px + kx - 1;
        float v = 0.0f;
        if ((unsigned)iy < 3u && (unsigned)ix < 3u)
            v = rn[c * 9 + iy * 3 + ix];
        row[k] = v;
    }
}

// ---------------------------------------------------------------------------
// K2: 3xTF32 mma.sync GEMM.  h[m,e] = sum_k A[m,k]*W[e,k]  (both K-major ->
// row.col mma with B = conv_w rows as "columns").
// grid (9 m-tiles, 2 n-tiles, 8 k-splits) = 144 CTAs. 256 thr = 8 warps (4m x 2n).
// Warp tile 32x64. Smem single-buffer + register prefetch of next stage.
// ---------------------------------------------------------------------------
__global__ void __launch_bounds__(256, 1) k_gemm_mma(const float* __restrict__ conv_w)
{
    __shared__ float As[2][128 * SROW];   // [hi/lo][row*36 + k]
    __shared__ float Bs[2][128 * SROW];

    const int tid  = threadIdx.x;
    const int wid  = tid >> 5;
    const int lane = tid & 31;
    const int warp_m = wid & 3;        // 0..3 -> 32-row slice
    const int warp_n = wid >> 2;       // 0..1 -> 64-col slice

    const int m0 = blockIdx.x * 128;
    const int n0 = blockIdx.y * 128;
    const int k0 = blockIdx.z * KSLICE;

    // loader mapping: idx = tid + q*256; row = idx>>3; colv = idx&7 (float4)
    const int lrow = tid >> 3;          // base row for q=0 (rows 0..31)
    const int lcol = (tid & 7) * 4;     // float k-offset

    float acc[2][8][4];
    #pragma unroll
    for (int i = 0; i < 2; i++)
        #pragma unroll
        for (int j = 0; j < 8; j++)
            #pragma unroll
            for (int q = 0; q < 4; q++) acc[i][j][q] = 0.0f;

    const float* __restrict__ Abase = g_A    + (size_t)m0 * K_GEMM + k0;
    const float* __restrict__ Bbase = conv_w + (size_t)n0 * K_GEMM + k0;

    float4 ra[4], rb[4];
    // prefetch stage 0
    #pragma unroll
    for (int q = 0; q < 4; q++) {
        const int row = lrow + q * 32;
        ra[q] = *(const float4*)(Abase + (size_t)row * K_GEMM + lcol);
        rb[q] = *(const float4*)(Bbase + (size_t)row * K_GEMM + lcol);
    }

    for (int s = 0; s < NSTAGE; s++) {
        // split to hi/lo tf32 and store to smem
        #pragma unroll
        for (int q = 0; q < 4; q++) {
            const int row = lrow + q * 32;
            float4 h, l;
            h.x = f2tf32(ra[q].x); h.y = f2tf32(ra[q].y);
            h.z = f2tf32(ra[q].z); h.w = f2tf32(ra[q].w);
            l.x = f2tf32(ra[q].x - h.x); l.y = f2tf32(ra[q].y - h.y);
            l.z = f2tf32(ra[q].z - h.z); l.w = f2tf32(ra[q].w - h.w);
            *(float4*)(&As[0][row * SROW + lcol]) = h;
            *(float4*)(&As[1][row * SROW + lcol]) = l;
            h.x = f2tf32(rb[q].x); h.y = f2tf32(rb[q].y);
            h.z = f2tf32(rb[q].z); h.w = f2tf32(rb[q].w);
            l.x = f2tf32(rb[q].x - h.x); l.y = f2tf32(rb[q].y - h.y);
            l.z = f2tf32(rb[q].z - h.z); l.w = f2tf32(rb[q].w - h.w);
            *(float4*)(&Bs[0][row * SROW + lcol]) = h;
            *(float4*)(&Bs[1][row * SROW + lcol]) = l;
        }
        __syncthreads();

        // prefetch next stage (overlaps LDG latency with the mma stream)
        if (s + 1 < NSTAGE) {
            const int koff = (s + 1) * BK;
            #pragma unroll
            for (int q = 0; q < 4; q++) {
                const int row = lrow + q * 32;
                ra[q] = *(const float4*)(Abase + (size_t)row * K_GEMM + koff + lcol);
                rb[q] = *(const float4*)(Bbase + (size_t)row * K_GEMM + koff + lcol);
            }
        }

        // compute: 4 k-chunks of 8
        const int rbase = warp_m * 32 + (lane >> 2);
        const int nbase = warp_n * 64 + (lane >> 2);
        #pragma unroll
        for (int kc = 0; kc < 4; kc++) {
            const int kb = kc * 8 + (lane & 3);
            uint32_t ah[2][4], al[2][4];
            #pragma unroll
            for (int i = 0; i < 2; i++) {
                const int r = rbase + i * 16;
                ah[i][0] = __float_as_uint(As[0][r * SROW + kb]);
                ah[i][1] = __float_as_uint(As[0][(r + 8) * SROW + kb]);
                ah[i][2] = __float_as_uint(As[0][r * SROW + kb + 4]);
                ah[i][3] = __float_as_uint(As[0][(r + 8) * SROW + kb + 4]);
                al[i][0] = __float_as_uint(As[1][r * SROW + kb]);
                al[i][1] = __float_as_uint(As[1][(r + 8) * SROW + kb]);
                al[i][2] = __float_as_uint(As[1][r * SROW + kb + 4]);
                al[i][3] = __float_as_uint(As[1][(r + 8) * SROW + kb + 4]);
            }
            #pragma unroll
            for (int j = 0; j < 8; j++) {
                const int nn = nbase + j * 8;
                const uint32_t bh0 = __float_as_uint(Bs[0][nn * SROW + kb]);
                const uint32_t bh1 = __float_as_uint(Bs[0][nn * SROW + kb + 4]);
                const uint32_t bl0 = __float_as_uint(Bs[1][nn * SROW + kb]);
                const uint32_t bl1 = __float_as_uint(Bs[1][nn * SROW + kb + 4]);
                #pragma unroll
                for (int i = 0; i < 2; i++) {
                    mma_tf32(acc[i][j], ah[i][0], ah[i][1], ah[i][2], ah[i][3], bh0, bh1);
                    mma_tf32(acc[i][j], ah[i][0], ah[i][1], ah[i][2], ah[i][3], bl0, bl1);
                    mma_tf32(acc[i][j], al[i][0], al[i][1], al[i][2], al[i][3], bh0, bh1);
                }
            }
        }
        __syncthreads();
    }

    // write split-K partials
    float* __restrict__ hp = g_hpart + (size_t)blockIdx.z * ((size_t)M_GEMM * N_GEMM);
    #pragma unroll
    for (int i = 0; i < 2; i++) {
        const int row = m0 + warp_m * 32 + i * 16 + (lane >> 2);
        #pragma unroll
        for (int j = 0; j < 8; j++) {
            const int col = n0 + warp_n * 64 + j * 8 + 2 * (lane & 3);
            *(float2*)(hp + (size_t)row * N_GEMM + col) =
                make_float2(acc[i][j][0], acc[i][j][1]);
            *(float2*)(hp + (size_t)(row + 8) * N_GEMM + col) =
                make_float2(acc[i][j][2], acc[i][j][3]);
        }
    }
}

// ---------------------------------------------------------------------------
// K3: per-roi epilogue.
// ---------------------------------------------------------------------------
__global__ void __launch_bounds__(256) k_epilogue(
    const float* __restrict__ boxes,
    const float* __restrict__ gn_scale, const float* __restrict__ gn_bias,
    const float* __restrict__ head_w,   const float* __restrict__ head_b,
    const float* __restrict__ spat_w,   const float* __restrict__ spat_b,
    const float* __restrict__ sym_emb,
    const float* __restrict__ fuse_w,   const float* __restrict__ fuse_b,
    const int*   __restrict__ sym_ids,
    float* __restrict__ out)
{
    const int n = blockIdx.x;
    const int e = threadIdx.x;

    float hvp[9];
    #pragma unroll
    for (int p = 0; p < 9; p++) {
        float s = 0.0f;
        #pragma unroll
        for (int sp = 0; sp < SPLITK; sp++)
            s += g_hpart[(size_t)sp * ((size_t)M_GEMM * N_GEMM) + (size_t)(n*9 + p) * N_GEMM + e];
        hvp[p] = s;
    }

    float lsum = 0.0f;
    #pragma unroll
    for (int p = 0; p < 9; p++) lsum += hvp[p];
    #pragma unroll
    for (int o = 16; o > 0; o >>= 1) lsum += __shfl_xor_sync(0xffffffffu, lsum, o);
    const float mean = lsum * (1.0f / 288.0f);

    float lsq = 0.0f;
    #pragma unroll
    for (int p = 0; p < 9; p++) { float d = hvp[p] - mean; lsq += d * d; }
    #pragma unroll
    for (int o = 16; o > 0; o >>= 1) lsq += __shfl_xor_sync(0xffffffffu, lsq, o);
    const float var = lsq * (1.0f / 288.0f);
    const float inv = rsqrtf(var + 1e-5f);

    const float sc = gn_scale[e];
    const float bi = gn_bias[e];
    float acc = 0.0f;
    #pragma unroll
    for (int p = 0; p < 9; p++)
        acc += fmaxf((hvp[p] - mean) * inv * sc + bi, 0.0f);
    const float sval = acc * (1.0f / 9.0f);

    __shared__ float sbuf[256];
    sbuf[e] = sval;
    __syncthreads();

    float ho = head_b[e];
    const float* __restrict__ hw = head_w + (size_t)e * 256;
    #pragma unroll 8
    for (int j = 0; j < 256; j += 4) {
        const float4 w = *(const float4*)(hw + j);
        ho += sbuf[j]   * w.x + sbuf[j+1] * w.y
            + sbuf[j+2] * w.z + sbuf[j+3] * w.w;
    }
    ho = fmaxf(ho, 0.0f);

    const float b0 = boxes[n*4+0], b1 = boxes[n*4+1], b2 = boxes[n*4+2], b3 = boxes[n*4+3];
    float sp = spat_b[e] + b0 * spat_w[e*4+0] + b1 * spat_w[e*4+1]
                         + b2 * spat_w[e*4+2] + b3 * spat_w[e*4+3];
    sp = fmaxf(sp, 0.0f);

    const int sym = sym_ids[n];
    const float fused = ho + sp + sym_emb[sym * 256 + e];

    __syncthreads();
    sbuf[e] = fused;
    __syncthreads();

    float o = fuse_b[sym * 256 + e];
    const float* __restrict__ fw = fuse_w + ((size_t)sym * 256 + e) * 256;
    #pragma unroll 8
    for (int j = 0; j < 256; j += 4) {
        const float4 w = *(const float4*)(fw + j);
        o += sbuf[j]   * w.x + sbuf[j+1] * w.y
           + sbuf[j+2] * w.z + sbuf[j+3] * w.w;
    }
    out[(size_t)n * 256 + e] = fmaxf(o, 0.0f);
}

// ---------------------------------------------------------------------------
extern "C" void kernel_launch(void* const* d_in, const int* in_sizes, int n_in,
                              void* d_out, int out_size)
{
    const float* fm        = (const float*)d_in[0];
    const float* boxes     = (const float*)d_in[1];
    const float* conv_w    = (const float*)d_in[2];
    const float* gn_scale  = (const float*)d_in[3];
    const float* gn_bias   = (const float*)d_in[4];
    const float* head_w    = (const float*)d_in[5];
    const float* head_b    = (const float*)d_in[6];
    const float* spat_w    = (const float*)d_in[7];
    const float* spat_b    = (const float*)d_in[8];
    const float* sym_emb   = (const float*)d_in[9];
    const float* fuse_w    = (const float*)d_in[10];
    const float* fuse_b    = (const float*)d_in[11];
    const int*   batch_idx = (const int*)d_in[12];
    const int*   level_idx = (const int*)d_in[13];
    const int*   sym_ids   = (const int*)d_in[14];
    float* out = (float*)d_out;

    dim3 g1(NROI, 4);
    k_roi<<<g1, 64>>>(fm, boxes, batch_idx, level_idx);

    k_im2col<<<M_GEMM, 256>>>();

    dim3 g2(M_GEMM / 128, N_GEMM / 128, SPLITK);   // (9, 2, 8) = 144 CTAs
    k_gemm_mma<<<g2, 256>>>(conv_w);

    k_epilogue<<<NROI, 256>>>(boxes, gn_scale, gn_bias, head_w, head_b,
                              spat_w, spat_b, sym_emb, fuse_w, fuse_b,
                              sym_ids, out);
}